// round 4
// baseline (speedup 1.0000x reference)
#include <cuda_runtime.h>
#include <math.h>

// ---------------------------------------------------------------------------
// SwinTransformerBlock3D — fp32, f32x2 FMA, smem-resident weights (sm_103a)
// 4 kernels: K1 LN1+QKV, K2 window attention+proj, K4 LN2+MLP1, K5 MLP2
// ---------------------------------------------------------------------------

#define LTOK (16*64*64)        // 65536 tokens per batch
#define BATCH 2
#define C 96
#define NH 6
#define HD 16
#define NW 64
#define MLPH 384
#define NTILE 2048             // (BATCH*LTOK)/64

typedef unsigned long long u64t;

// global scratch (device globals — no allocation)
__device__ float g_ybuf[(size_t)BATCH * LTOK * C];        //  50 MB
__device__ float g_qkv [(size_t)BATCH * LTOK * 3 * C];    // 151 MB
__device__ float g_hid [(size_t)BATCH * LTOK * MLPH];     // 201 MB

// ---------------- helpers --------------------------------------------------
__device__ __forceinline__ unsigned sp(const void* p) {
    return (unsigned)__cvta_generic_to_shared(p);
}
__device__ __forceinline__ u64t ldsb64(const float* p) {
    u64t v; asm volatile("ld.shared.b64 %0,[%1];" : "=l"(v) : "r"(sp(p))); return v;
}
__device__ __forceinline__ void ldsv2b64(u64t& a, u64t& b, const float* p) {
    asm volatile("ld.shared.v2.b64 {%0,%1},[%2];" : "=l"(a), "=l"(b) : "r"(sp(p)));
}
__device__ __forceinline__ float2 ldsf2(const float* p) {
    float2 r; asm volatile("ld.shared.v2.f32 {%0,%1},[%2];"
                           : "=f"(r.x), "=f"(r.y) : "r"(sp(p))); return r;
}
__device__ __forceinline__ float4 ldsf4(const float* p) {
    float4 r; asm volatile("ld.shared.v4.f32 {%0,%1,%2,%3},[%4];"
                           : "=f"(r.x),"=f"(r.y),"=f"(r.z),"=f"(r.w) : "r"(sp(p))); return r;
}
__device__ __forceinline__ u64t pk2(float x, float y) {
    u64t r; asm("mov.b64 %0,{%1,%2};" : "=l"(r) : "f"(x), "f"(y)); return r;
}
__device__ __forceinline__ u64t dup2(float x) { return pk2(x, x); }
__device__ __forceinline__ float2 up2(u64t v) {
    float2 r; asm("mov.b64 {%0,%1},%2;" : "=f"(r.x), "=f"(r.y) : "l"(v)); return r;
}
__device__ __forceinline__ void fma2(u64t& d, u64t a, u64t b) {
    asm("fma.rn.f32x2 %0,%1,%2,%0;" : "+l"(d) : "l"(a), "l"(b));
}

// mbarrier + cp.async.bulk (weights -> smem)
__device__ __forceinline__ void mbar_init(float* mbar) {
    asm volatile("mbarrier.init.shared.b64 [%0], 1;" :: "r"(sp(mbar)) : "memory");
}
__device__ __forceinline__ void fence_async() {
    asm volatile("fence.proxy.async.shared::cta;" ::: "memory");
}
__device__ __forceinline__ void bulk_ld(float* dst, const float* src,
                                        unsigned bytes, float* mbar) {
    asm volatile("mbarrier.arrive.expect_tx.shared.b64 _, [%0], %1;"
                 :: "r"(sp(mbar)), "r"(bytes) : "memory");
    asm volatile("cp.async.bulk.shared::cta.global.mbarrier::complete_tx::bytes "
                 "[%0], [%1], %2, [%3];"
                 :: "r"(sp(dst)), "l"(src), "r"(bytes), "r"(sp(mbar)) : "memory");
}
__device__ __forceinline__ void mbar_wait0(float* mbar) {
    unsigned ph = 0;
    asm volatile(
        "{\n\t"
        ".reg .pred P;\n"
        "W%=:\n\t"
        "mbarrier.try_wait.parity.shared::cta.b64 P, [%0], %1;\n\t"
        "@P bra D%=;\n\t"
        "bra W%=;\n"
        "D%=:\n\t"
        "}" :: "r"(sp(mbar)), "r"(ph) : "memory");
}

// ===========================================================================
// K1: LN1 + QKV GEMM  (qkv_w in smem) -> g_qkv[token][288]
// 256 threads, tile = 64 contiguous tokens
// ===========================================================================
#define K1_WS 0
#define K1_XS 27648
#define K1_MB 34048
#define K1_TOT 34052

__global__ __launch_bounds__(256, 1)
void ln1_qkv_kernel(const float* __restrict__ x,
                    const float* __restrict__ g1, const float* __restrict__ b1,
                    const float* __restrict__ qkv_w, const float* __restrict__ qkv_b)
{
    extern __shared__ float smf[];
    float* ws = smf + K1_WS;
    float* xs = smf + K1_XS;
    float* mb = smf + K1_MB;

    const int tid = threadIdx.x;
    const int t0 = blockIdx.x * NW;

    if (tid == 0) {
        mbar_init(mb);
        fence_async();
        bulk_ld(ws, qkv_w, 96u * 288u * 4u, mb);
    }

    // LN1: 4 lanes per token, 24 ch each
    {
        const int n = tid >> 2, q = tid & 3;
        const float* xr = x + (size_t)(t0 + n) * C + q * 24;
        float v[24]; float s = 0.f, ss = 0.f;
        #pragma unroll
        for (int j = 0; j < 24; j++) { float t = xr[j]; v[j] = t; s += t; ss += t * t; }
        s  += __shfl_xor_sync(0xffffffffu, s, 1);  ss += __shfl_xor_sync(0xffffffffu, ss, 1);
        s  += __shfl_xor_sync(0xffffffffu, s, 2);  ss += __shfl_xor_sync(0xffffffffu, ss, 2);
        float mean = s * (1.f / 96.f);
        float var  = ss * (1.f / 96.f) - mean * mean;
        float rstd = rsqrtf(var + 1e-5f);
        #pragma unroll
        for (int j = 0; j < 24; j++) {
            int c = q * 24 + j;
            xs[n * 100 + c] = (v[j] - mean) * rstd * __ldg(g1 + c) + __ldg(b1 + c);
        }
    }
    __syncthreads();
    mbar_wait0(mb);

    // GEMM [64x96]@[96x288]: 8 rows x (4 col-pairs + 1 scalar col) per thread
    {
        const int rg = tid >> 5, lane = tid & 31;
        const int r0 = rg * 8;
        u64t acc2[8][4]; float accs[8];
        #pragma unroll
        for (int j = 0; j < 4; j++) {
            float2 bv = __ldg((const float2*)(qkv_b + 2 * lane + 64 * j));
            u64t bj = pk2(bv.x, bv.y);
            #pragma unroll
            for (int r = 0; r < 8; r++) acc2[r][j] = bj;
        }
        {
            float bs = __ldg(qkv_b + 256 + lane);
            #pragma unroll
            for (int r = 0; r < 8; r++) accs[r] = bs;
        }
        #pragma unroll 2
        for (int k = 0; k < C; k++) {
            float asv[8]; u64t ad[8];
            #pragma unroll
            for (int r = 0; r < 8; r++) { asv[r] = xs[(r0 + r) * 100 + k]; ad[r] = dup2(asv[r]); }
            #pragma unroll
            for (int j = 0; j < 4; j++) {
                u64t wp = ldsb64(ws + k * 288 + 2 * lane + 64 * j);
                #pragma unroll
                for (int r = 0; r < 8; r++) fma2(acc2[r][j], ad[r], wp);
            }
            float wsc = ws[k * 288 + 256 + lane];
            #pragma unroll
            for (int r = 0; r < 8; r++) accs[r] = fmaf(asv[r], wsc, accs[r]);
        }
        #pragma unroll
        for (int r = 0; r < 8; r++) {
            size_t base = (size_t)(t0 + r0 + r) * 288;
            #pragma unroll
            for (int j = 0; j < 4; j++) {
                float2 t = up2(acc2[r][j]);
                *(float2*)(g_qkv + base + 2 * lane + 64 * j) = make_float2(t.x, t.y);
            }
            g_qkv[base + 256 + lane] = accs[r];
        }
    }
}

// ===========================================================================
// K2: window gather + attention + proj (+residual) -> g_ybuf
// 512 threads, one block per window
// ===========================================================================
#define K2_RAW 0
#define K2_KT  18432
#define K2_SB  24960
#define K2_OT  29312
#define K2_PW  35840
#define K2_BIA 45056
#define K2_REL 47114
#define K2_SRC 49162
#define K2_MB  49226
#define K2_TOT 49228

__global__ __launch_bounds__(512, 1)
void attn_kernel(const float* __restrict__ x,
                 const float* __restrict__ proj_w, const float* __restrict__ proj_b,
                 const float* __restrict__ bias_table)
{
    extern __shared__ float smf[];
    float* raw  = smf + K2_RAW;     // [64][288] gathered qkv, later red [64][100]
    float* kT   = smf + K2_KT;      // [96][68]
    float* sbuf = smf + K2_SB;      // [64][68]
    float* oT   = smf + K2_OT;      // [96][68]
    float* pw   = smf + K2_PW;      // [96*96]
    float* sbias = smf + K2_BIA;
    unsigned short* rel = (unsigned short*)(smf + K2_REL);
    int* srcidx = (int*)(smf + K2_SRC);
    float* mb = smf + K2_MB;

    const int tid = threadIdx.x;
    const int wb = blockIdx.x;
    const int bb = wb >> 10;
    const int w  = wb & 1023;
    const int iw = w >> 8, xw = (w >> 4) & 15, tw = w & 15;

    if (tid == 0) {
        mbar_init(mb);
        fence_async();
        bulk_ld(pw, proj_w, 96u * 96u * 4u, mb);
    }

    if (tid < NW) {
        int i = tid >> 4, xx = (tid >> 2) & 3, tt = tid & 3;
        int gi = (iw * 4 + i  + 2) & 15;
        int gx = (xw * 4 + xx + 2) & 63;
        int gt = (tw * 4 + tt + 2) & 63;
        srcidx[tid] = ((gi << 6) + gx) * 64 + gt;
    }
    for (int p = tid; p < 4096; p += 512) {
        int n = p >> 6, m = p & 63;
        int di = (n >> 4)       - (m >> 4)       + 3;
        int dx = ((n >> 2) & 3) - ((m >> 2) & 3) + 3;
        int dt = (n & 3)        - (m & 3)        + 3;
        rel[p] = (unsigned short)((di * 7 + dx) * 7 + dt);
    }
    for (int i = tid; i < 343 * NH; i += 512) sbias[i] = __ldg(bias_table + i);

    // gather qkv rows (shift applied via src index, computed inline)
    {
        const int n = tid >> 3, q8 = tid & 7;
        int i2 = n >> 4, xx = (n >> 2) & 3, tt = n & 3;
        int gi = (iw * 4 + i2 + 2) & 15;
        int gx = (xw * 4 + xx + 2) & 63;
        int gt = (tw * 4 + tt + 2) & 63;
        int src = ((gi << 6) + gx) * 64 + gt;
        const float4* srcp = (const float4*)(g_qkv + (size_t)(bb * LTOK + src) * 288 + q8 * 36);
        float4* dstp = (float4*)(raw + n * 288 + q8 * 36);
        #pragma unroll
        for (int i = 0; i < 9; i++) dstp[i] = __ldg(srcp + i);
    }
    __syncthreads();

    // transpose K part -> kT[c][n]
    for (int idx = tid; idx < 96 * 64; idx += 512) {
        int n = idx / 96, c = idx - n * 96;
        kT[c * 68 + n] = raw[n * 288 + 96 + c];
    }
    __syncthreads();

    // attention: row n = tid>>3, sub = tid&7 (cols m0..m0+7, dims 2*sub..+1)
    {
        const int n = tid >> 3, sub = tid & 7;
        const int m0 = sub * 8;
        #pragma unroll 1
        for (int h = 0; h < NH; h++) {
            const int hb = h * HD;
            u64t qd[HD];
            #pragma unroll
            for (int dd = 0; dd < HD; dd++) qd[dd] = dup2(raw[n * 288 + hb + dd]);

            u64t p2[4] = {0ull, 0ull, 0ull, 0ull};
            #pragma unroll
            for (int dd = 0; dd < HD; dd++) {
                const float* kp = kT + (hb + dd) * 68 + m0;
                u64t k01, k23, k45, k67;
                ldsv2b64(k01, k23, kp);
                ldsv2b64(k45, k67, kp + 4);
                fma2(p2[0], qd[dd], k01); fma2(p2[1], qd[dd], k23);
                fma2(p2[2], qd[dd], k45); fma2(p2[3], qd[dd], k67);
            }
            float p[8];
            #pragma unroll
            for (int i = 0; i < 4; i++) { float2 t = up2(p2[i]); p[2*i] = t.x; p[2*i+1] = t.y; }
            #pragma unroll
            for (int i = 0; i < 8; i++) {
                int rdx = rel[n * 64 + m0 + i];
                p[i] = p[i] * 0.25f + sbias[rdx * NH + h];
            }
            float mx = -1e30f;
            #pragma unroll
            for (int i = 0; i < 8; i++) mx = fmaxf(mx, p[i]);
            mx = fmaxf(mx, __shfl_xor_sync(0xffffffffu, mx, 1));
            mx = fmaxf(mx, __shfl_xor_sync(0xffffffffu, mx, 2));
            mx = fmaxf(mx, __shfl_xor_sync(0xffffffffu, mx, 4));
            float sum = 0.f;
            #pragma unroll
            for (int i = 0; i < 8; i++) { p[i] = __expf(p[i] - mx); sum += p[i]; }
            sum += __shfl_xor_sync(0xffffffffu, sum, 1);
            sum += __shfl_xor_sync(0xffffffffu, sum, 2);
            sum += __shfl_xor_sync(0xffffffffu, sum, 4);
            float inv = 1.f / sum;
            #pragma unroll
            for (int i = 0; i < 8; i++) sbuf[n * 68 + m0 + i] = p[i] * inv;
            __syncwarp();

            // AV
            float o0 = 0.f, o1 = 0.f, o0b = 0.f, o1b = 0.f;
            const float* vb = raw + 192 + hb + sub * 2;
            #pragma unroll
            for (int m4 = 0; m4 < 16; m4++) {
                float4 pr = ldsf4(sbuf + n * 68 + m4 * 4);
                const float* vm = vb + (m4 * 4) * 288;
                float2 v0 = ldsf2(vm);         o0  += pr.x * v0.x; o1  += pr.x * v0.y;
                float2 v1 = ldsf2(vm + 288);   o0b += pr.y * v1.x; o1b += pr.y * v1.y;
                float2 v2 = ldsf2(vm + 576);   o0  += pr.z * v2.x; o1  += pr.z * v2.y;
                float2 v3 = ldsf2(vm + 864);   o0b += pr.w * v3.x; o1b += pr.w * v3.y;
            }
            oT[(hb + sub * 2) * 68 + n]     = o0 + o0b;
            oT[(hb + sub * 2 + 1) * 68 + n] = o1 + o1b;
            __syncwarp();
        }
    }
    __syncthreads();
    mbar_wait0(mb);

    // proj [64x96]@[96x96], split-K 2 + residual -> g_ybuf (scattered rows)
    {
        const int kh = tid >> 8;
        const int t2 = tid & 255;
        const int rg = t2 >> 5, lane = t2 & 31;
        const int r0 = rg * 8;
        u64t acc[4][3];
        #pragma unroll
        for (int j = 0; j < 3; j++) {
            u64t bj = (kh == 0) ? dup2(__ldg(proj_b + lane + 32 * j)) : 0ull;
            #pragma unroll
            for (int p = 0; p < 4; p++) acc[p][j] = bj;
        }
        const int k0 = kh * 48;
        #pragma unroll 2
        for (int kk = 0; kk < 48; kk++) {
            int k = k0 + kk;
            u64t a[4];
            #pragma unroll
            for (int p = 0; p < 4; p++) a[p] = ldsb64(oT + k * 68 + r0 + 2 * p);
            #pragma unroll
            for (int j = 0; j < 3; j++) {
                u64t wd = dup2(pw[k * 96 + lane + 32 * j]);
                #pragma unroll
                for (int p = 0; p < 4; p++) fma2(acc[p][j], a[p], wd);
            }
        }
        float* red = raw;   // raw free now: [64][100]
        if (kh == 1) {
            #pragma unroll
            for (int p = 0; p < 4; p++) {
                int r = r0 + 2 * p;
                #pragma unroll
                for (int j = 0; j < 3; j++) {
                    int c = lane + 32 * j;
                    float2 t = up2(acc[p][j]);
                    red[r * 100 + c] = t.x;
                    red[(r + 1) * 100 + c] = t.y;
                }
            }
        }
        __syncthreads();
        if (kh == 0) {
            #pragma unroll
            for (int p = 0; p < 4; p++) {
                int r = r0 + 2 * p;
                size_t b0 = (size_t)(bb * LTOK + srcidx[r]) * C;
                size_t b1 = (size_t)(bb * LTOK + srcidx[r + 1]) * C;
                #pragma unroll
                for (int j = 0; j < 3; j++) {
                    int c = lane + 32 * j;
                    float2 t = up2(acc[p][j]);
                    g_ybuf[b0 + c] = x[b0 + c] + t.x + red[r * 100 + c];
                    g_ybuf[b1 + c] = x[b1 + c] + t.y + red[(r + 1) * 100 + c];
                }
            }
        }
    }
}

// ===========================================================================
// K4: LN2 + MLP GEMM1 + GELU (w1 in smem) -> g_hid[token][384]
// 256 threads, tile = 64 tokens
// ===========================================================================
#define K4_WS 0
#define K4_XS 36864
#define K4_MB 43264
#define K4_TOT 43266

__global__ __launch_bounds__(256, 1)
void ln2_mlp1_kernel(const float* __restrict__ g2, const float* __restrict__ b2,
                     const float* __restrict__ w1, const float* __restrict__ bb1)
{
    extern __shared__ float smf[];
    float* ws = smf + K4_WS;
    float* xs = smf + K4_XS;
    float* mb = smf + K4_MB;

    const int tid = threadIdx.x;
    const int t0 = blockIdx.x * NW;

    if (tid == 0) {
        mbar_init(mb);
        fence_async();
        bulk_ld(ws, w1, 96u * 384u * 4u, mb);
    }

    // LN2
    {
        const int n = tid >> 2, q = tid & 3;
        const float* yr = g_ybuf + (size_t)(t0 + n) * C + q * 24;
        float v[24]; float s = 0.f, ss = 0.f;
        #pragma unroll
        for (int j = 0; j < 24; j++) { float t = yr[j]; v[j] = t; s += t; ss += t * t; }
        s  += __shfl_xor_sync(0xffffffffu, s, 1);  ss += __shfl_xor_sync(0xffffffffu, ss, 1);
        s  += __shfl_xor_sync(0xffffffffu, s, 2);  ss += __shfl_xor_sync(0xffffffffu, ss, 2);
        float mean = s * (1.f / 96.f);
        float var  = ss * (1.f / 96.f) - mean * mean;
        float rstd = rsqrtf(var + 1e-5f);
        #pragma unroll
        for (int j = 0; j < 24; j++) {
            int c = q * 24 + j;
            xs[n * 100 + c] = (v[j] - mean) * rstd * __ldg(g2 + c) + __ldg(b2 + c);
        }
    }
    __syncthreads();
    mbar_wait0(mb);

    // GEMM [64x96]@[96x384]: 8 rows x 6 col-pairs per thread
    {
        const int rg = tid >> 5, lane = tid & 31;
        const int r0 = rg * 8;
        u64t acc2[8][6];
        #pragma unroll
        for (int j = 0; j < 6; j++) {
            float2 bv = __ldg((const float2*)(bb1 + 2 * lane + 64 * j));
            u64t bj = pk2(bv.x, bv.y);
            #pragma unroll
            for (int r = 0; r < 8; r++) acc2[r][j] = bj;
        }
        #pragma unroll 2
        for (int k = 0; k < C; k++) {
            u64t ad[8];
            #pragma unroll
            for (int r = 0; r < 8; r++) ad[r] = dup2(xs[(r0 + r) * 100 + k]);
            #pragma unroll
            for (int j = 0; j < 6; j++) {
                u64t wp = ldsb64(ws + k * 384 + 2 * lane + 64 * j);
                #pragma unroll
                for (int r = 0; r < 8; r++) fma2(acc2[r][j], ad[r], wp);
            }
        }
        #pragma unroll
        for (int r = 0; r < 8; r++) {
            size_t base = (size_t)(t0 + r0 + r) * MLPH;
            #pragma unroll
            for (int j = 0; j < 6; j++) {
                float2 t = up2(acc2[r][j]);
                float gx = 0.5f * t.x * (1.0f + erff(t.x * 0.70710678118654752f));
                float gy = 0.5f * t.y * (1.0f + erff(t.y * 0.70710678118654752f));
                *(float2*)(g_hid + base + 2 * lane + 64 * j) = make_float2(gx, gy);
            }
        }
    }
}

// ===========================================================================
// K5: MLP GEMM2 (w2 in smem, hid transpose-staged in chunks) + residual -> out
// 512 threads (split-K 2), tile = 64 tokens
// ===========================================================================
#define K5_WS  0
#define K5_HB  36864
#define K5_RED 45312
#define K5_MB  51712
#define K5_TOT 51714

__global__ __launch_bounds__(512, 1)
void mlp2_kernel(const float* __restrict__ w2, const float* __restrict__ bb2,
                 float* __restrict__ out)
{
    extern __shared__ float smf[];
    float* ws = smf + K5_WS;
    float* hb = smf + K5_HB;        // 2 x [64k][66]
    float* red = smf + K5_RED;      // [64][100]
    float* mb = smf + K5_MB;

    const int tid = threadIdx.x;
    const int t0 = blockIdx.x * NW;

    if (tid == 0) {
        mbar_init(mb);
        fence_async();
        bulk_ld(ws, w2, 384u * 96u * 4u, mb);
    }

    const int kh = tid >> 8;
    const int t2 = tid & 255;
    const int rg = t2 >> 5, lane = t2 & 31;
    const int r0 = rg * 8;
    u64t acc[4][3];
    #pragma unroll
    for (int j = 0; j < 3; j++) {
        u64t bj = (kh == 0) ? dup2(__ldg(bb2 + lane + 32 * j)) : 0ull;
        #pragma unroll
        for (int p = 0; p < 4; p++) acc[p][j] = bj;
    }
    __syncthreads();
    mbar_wait0(mb);

    const int sn = tid >> 3, sq = tid & 7;
    #pragma unroll 1
    for (int cc = 0; cc < 3; cc++) {
        // stage chunk cc of both k-halves, transposed -> hb[h][k][n]
        #pragma unroll
        for (int h = 0; h < 2; h++) {
            const float* src = g_hid + (size_t)(t0 + sn) * MLPH + h * 192 + cc * 64 + sq * 8;
            float4 A = __ldg((const float4*)src);
            float4 Bv = __ldg((const float4*)(src + 4));
            float* dst = hb + h * 4224;
            int kb = sq * 8;
            dst[(kb + 0) * 66 + sn] = A.x;  dst[(kb + 1) * 66 + sn] = A.y;
            dst[(kb + 2) * 66 + sn] = A.z;  dst[(kb + 3) * 66 + sn] = A.w;
            dst[(kb + 4) * 66 + sn] = Bv.x; dst[(kb + 5) * 66 + sn] = Bv.y;
            dst[(kb + 6) * 66 + sn] = Bv.z; dst[(kb + 7) * 66 + sn] = Bv.w;
        }
        __syncthreads();

        const float* hbm = hb + kh * 4224;
        const int kbase = kh * 192 + cc * 64;
        #pragma unroll 2
        for (int kk = 0; kk < 64; kk++) {
            u64t a[4];
            #pragma unroll
            for (int p = 0; p < 4; p++) a[p] = ldsb64(hbm + kk * 66 + r0 + 2 * p);
            const float* wr = ws + (kbase + kk) * 96 + lane;
            #pragma unroll
            for (int j = 0; j < 3; j++) {
                u64t wd = dup2(wr[32 * j]);
                #pragma unroll
                for (int p = 0; p < 4; p++) fma2(acc[p][j], a[p], wd);
            }
        }
        __syncthreads();
    }

    // cross-half reduce + residual + store
    if (kh == 1) {
        #pragma unroll
        for (int p = 0; p < 4; p++) {
            int r = r0 + 2 * p;
            #pragma unroll
            for (int j = 0; j < 3; j++) {
                int c = lane + 32 * j;
                float2 t = up2(acc[p][j]);
                red[r * 100 + c] = t.x;
                red[(r + 1) * 100 + c] = t.y;
            }
        }
    }
    __syncthreads();
    if (kh == 0) {
        #pragma unroll
        for (int p = 0; p < 4; p++) {
            int r = r0 + 2 * p;
            size_t b0 = (size_t)(t0 + r) * C;
            size_t b1 = (size_t)(t0 + r + 1) * C;
            #pragma unroll
            for (int j = 0; j < 3; j++) {
                int c = lane + 32 * j;
                float2 t = up2(acc[p][j]);
                out[b0 + c] = g_ybuf[b0 + c] + t.x + red[r * 100 + c];
                out[b1 + c] = g_ybuf[b1 + c] + t.y + red[(r + 1) * 100 + c];
            }
        }
    }
}

// ---------------------------------------------------------------------------
extern "C" void kernel_launch(void* const* d_in, const int* in_sizes, int n_in,
                              void* d_out, int out_size)
{
    const float* x        = (const float*)d_in[0];
    const float* norm1_g  = (const float*)d_in[1];
    const float* norm1_b  = (const float*)d_in[2];
    const float* qkv_w    = (const float*)d_in[3];
    const float* qkv_b    = (const float*)d_in[4];
    const float* proj_w   = (const float*)d_in[5];
    const float* proj_b   = (const float*)d_in[6];
    const float* bias_tab = (const float*)d_in[7];
    const float* norm2_g  = (const float*)d_in[8];
    const float* norm2_b  = (const float*)d_in[9];
    const float* mlp_w1   = (const float*)d_in[10];
    const float* mlp_b1   = (const float*)d_in[11];
    const float* mlp_w2   = (const float*)d_in[12];
    const float* mlp_b2   = (const float*)d_in[13];
    float* out = (float*)d_out;

    cudaFuncSetAttribute(ln1_qkv_kernel,
                         cudaFuncAttributeMaxDynamicSharedMemorySize, K1_TOT * 4);
    cudaFuncSetAttribute(attn_kernel,
                         cudaFuncAttributeMaxDynamicSharedMemorySize, K2_TOT * 4);
    cudaFuncSetAttribute(ln2_mlp1_kernel,
                         cudaFuncAttributeMaxDynamicSharedMemorySize, K4_TOT * 4);
    cudaFuncSetAttribute(mlp2_kernel,
                         cudaFuncAttributeMaxDynamicSharedMemorySize, K5_TOT * 4);

    ln1_qkv_kernel<<<NTILE, 256, K1_TOT * 4>>>(x, norm1_g, norm1_b, qkv_w, qkv_b);
    attn_kernel<<<NTILE, 512, K2_TOT * 4>>>(x, proj_w, proj_b, bias_tab);
    ln2_mlp1_kernel<<<NTILE, 256, K4_TOT * 4>>>(norm2_g, norm2_b, mlp_w1, mlp_b1);
    mlp2_kernel<<<NTILE, 512, K5_TOT * 4>>>(mlp_w2, mlp_b2, out);
}

// round 6
// speedup vs baseline: 1.5110x; 1.5110x over previous
#include <cuda_runtime.h>
#include <math.h>

// ---------------------------------------------------------------------------
// SwinTransformerBlock3D — fp32, f32x2 FMA with dup'd-activation smem layout
// 2 kernels: A = LN1+gather+QKV+attn+proj+residual, B = LN2+MLP+residual
// ---------------------------------------------------------------------------

#define LTOK (16*64*64)
#define BATCH 2
#define C 96
#define NH 6
#define HD 16
#define NW 64
#define MLPH 384
#define NTILE 2048

typedef unsigned long long u64t;

__device__ float g_ybuf[(size_t)BATCH * LTOK * C];

// ---------------- helpers --------------------------------------------------
__device__ __forceinline__ unsigned sp(const void* p) {
    return (unsigned)__cvta_generic_to_shared(p);
}
__device__ __forceinline__ u64t ldsb64(const float* p) {
    u64t v; asm volatile("ld.shared.b64 %0,[%1];" : "=l"(v) : "r"(sp(p))); return v;
}
__device__ __forceinline__ void ldsv2b64(u64t& a, u64t& b, const float* p) {
    asm volatile("ld.shared.v2.b64 {%0,%1},[%2];" : "=l"(a), "=l"(b) : "r"(sp(p)));
}
__device__ __forceinline__ float2 ldsf2(const float* p) {
    float2 r; asm volatile("ld.shared.v2.f32 {%0,%1},[%2];"
                           : "=f"(r.x), "=f"(r.y) : "r"(sp(p))); return r;
}
__device__ __forceinline__ float4 ldsf4(const float* p) {
    float4 r; asm volatile("ld.shared.v4.f32 {%0,%1,%2,%3},[%4];"
                           : "=f"(r.x),"=f"(r.y),"=f"(r.z),"=f"(r.w) : "r"(sp(p))); return r;
}
__device__ __forceinline__ void stsb64(float* p, u64t v) {
    asm volatile("st.shared.b64 [%0],%1;" :: "r"(sp(p)), "l"(v));
}
__device__ __forceinline__ u64t pk2(float x, float y) {
    u64t r; asm("mov.b64 %0,{%1,%2};" : "=l"(r) : "f"(x), "f"(y)); return r;
}
__device__ __forceinline__ u64t dup2(float x) { return pk2(x, x); }
__device__ __forceinline__ float2 up2(u64t v) {
    float2 r; asm("mov.b64 {%0,%1},%2;" : "=f"(r.x), "=f"(r.y) : "l"(v)); return r;
}
__device__ __forceinline__ void fma2(u64t& d, u64t a, u64t b) {
    asm("fma.rn.f32x2 %0,%1,%2,%0;" : "+l"(d) : "l"(a), "l"(b));
}
__device__ __forceinline__ u64t ldg64(const float* p) {
    return __ldg((const u64t*)p);
}

// kernel A smem (float offsets)
#define A_XD   0        // xdup [96][130] (dup pairs); reused as oT [96][68]
#define A_Q    12480    // qbuf [64][100]; reused as proj red [64][98]
#define A_KT   18880    // kT [96][68]
#define A_V    25408    // vbuf [64][100]
#define A_S    31808    // sbuf [64][68]
#define A_BIAS 36160    // 2058
#define A_REL  38218    // u16[4096]
#define A_SRC  40266    // int[64]
#define A_TOT  40330

// ===========================================================================
// Kernel A
// ===========================================================================
__global__ __launch_bounds__(512, 1)
void win_attn_kernel(const float* __restrict__ x,
                     const float* __restrict__ g1, const float* __restrict__ b1,
                     const float* __restrict__ qkv_w, const float* __restrict__ qkv_b,
                     const float* __restrict__ proj_w, const float* __restrict__ proj_b,
                     const float* __restrict__ bias_table)
{
    extern __shared__ float smf[];
    float* xdup = smf + A_XD;
    float* qbuf = smf + A_Q;
    float* kT   = smf + A_KT;
    float* vbuf = smf + A_V;
    float* sbuf = smf + A_S;
    float* sbias = smf + A_BIAS;
    unsigned short* rel = (unsigned short*)(smf + A_REL);
    int* srcidx = (int*)(smf + A_SRC);

    const int tid = threadIdx.x;
    const int wb = blockIdx.x;
    const int bb = wb >> 10;
    const int w  = wb & 1023;
    const int iw = w >> 8, xw = (w >> 4) & 15, tw = w & 15;

    if (tid < NW) {
        int i = tid >> 4, xx = (tid >> 2) & 3, tt = tid & 3;
        int gi = (iw * 4 + i  + 2) & 15;
        int gx = (xw * 4 + xx + 2) & 63;
        int gt = (tw * 4 + tt + 2) & 63;
        srcidx[tid] = ((gi << 6) + gx) * 64 + gt;
    }
    for (int p = tid; p < 4096; p += 512) {
        int n = p >> 6, m = p & 63;
        int di = (n >> 4)       - (m >> 4)       + 3;
        int dx = ((n >> 2) & 3) - ((m >> 2) & 3) + 3;
        int dt = (n & 3)        - (m & 3)        + 3;
        rel[p] = (unsigned short)((di * 7 + dx) * 7 + dt);
    }
    for (int i = tid; i < 343 * NH; i += 512) sbias[i] = __ldg(bias_table + i);
    __syncthreads();

    // ---- LN1: dup-pair store xdup[c][2n]
    {
        const int n = tid >> 3, q8 = tid & 7;
        const float* xr = x + ((size_t)(bb * LTOK + srcidx[n])) * C + q8 * 12;
        float v[12]; float s = 0.f, ss = 0.f;
        #pragma unroll
        for (int j = 0; j < 12; j++) { float t = xr[j]; v[j] = t; s += t; ss += t * t; }
        s  += __shfl_xor_sync(0xffffffffu, s, 1);  ss += __shfl_xor_sync(0xffffffffu, ss, 1);
        s  += __shfl_xor_sync(0xffffffffu, s, 2);  ss += __shfl_xor_sync(0xffffffffu, ss, 2);
        s  += __shfl_xor_sync(0xffffffffu, s, 4);  ss += __shfl_xor_sync(0xffffffffu, ss, 4);
        float mean = s * (1.f / 96.f);
        float var  = ss * (1.f / 96.f) - mean * mean;
        float rstd = rsqrtf(var + 1e-5f);
        #pragma unroll
        for (int j = 0; j < 12; j++) {
            int c = q8 * 12 + j;
            float val = (v[j] - mean) * rstd * __ldg(g1 + c) + __ldg(b1 + c);
            stsb64(xdup + c * 130 + 2 * n, dup2(val));
        }
    }
    __syncthreads();

    // ---- QKV GEMM [64x96]@[96x288]: col-pair packing, dup'd-a broadcast
    // thread: rg = tid>>5 (16 groups x 4 rows), lane = tid&31
    // cols: pairs (2*lane+64j, +1) j<4  + scalar col 256+lane
    {
        const int rg = tid >> 5, lane = tid & 31;
        const int r0 = rg * 4;
        u64t acc[4][4]; float accs[4];
        #pragma unroll
        for (int j = 0; j < 4; j++) {
            float2 bv = __ldg((const float2*)(qkv_b + 2 * lane + 64 * j));
            u64t bj = pk2(bv.x, bv.y);
            #pragma unroll
            for (int r = 0; r < 4; r++) acc[r][j] = bj;
        }
        {
            float bs = __ldg(qkv_b + 256 + lane);
            #pragma unroll
            for (int r = 0; r < 4; r++) accs[r] = bs;
        }
        #pragma unroll 2
        for (int k = 0; k < C; k++) {
            u64t ad[4];
            #pragma unroll
            for (int r = 0; r < 4; r++) ad[r] = ldsb64(xdup + k * 130 + 2 * (r0 + r));
            const float* wr = qkv_w + k * 288;
            #pragma unroll
            for (int j = 0; j < 4; j++) {
                u64t wp = ldg64(wr + 2 * lane + 64 * j);
                #pragma unroll
                for (int r = 0; r < 4; r++) fma2(acc[r][j], ad[r], wp);
            }
            float wsc = __ldg(wr + 256 + lane);
            #pragma unroll
            for (int r = 0; r < 4; r++) {
                float av = up2(ad[r]).x;
                accs[r] = fmaf(av, wsc, accs[r]);
            }
        }
        // scatter to qbuf / kT / vbuf
        #pragma unroll
        for (int r = 0; r < 4; r++) {
            int row = r0 + r;
            // j=0: cols 0..63 -> q
            stsb64(qbuf + row * 100 + 2 * lane, acc[r][0]);
            // j=1: cols 64..127 -> q (lane<16) or kT
            {
                int c0 = 64 + 2 * lane;
                if (c0 < 96) {
                    stsb64(qbuf + row * 100 + c0, acc[r][1]);
                } else {
                    float2 t = up2(acc[r][1]);
                    int kc = c0 - 96;
                    kT[kc * 68 + row] = t.x;
                    kT[(kc + 1) * 68 + row] = t.y;
                }
            }
            // j=2: cols 128..191 -> kT (kc 32..95)
            {
                float2 t = up2(acc[r][2]);
                int kc = 32 + 2 * lane;
                kT[kc * 68 + row] = t.x;
                kT[(kc + 1) * 68 + row] = t.y;
            }
            // j=3: cols 192..255 -> v cols 0..63
            stsb64(vbuf + row * 100 + 2 * lane, acc[r][3]);
            // scalar: col 256+lane -> v col 64+lane
            vbuf[row * 100 + 64 + lane] = accs[r];
        }
    }
    __syncthreads();

    float* oT = xdup;   // reuse (96x68 fits in 96x130)

    // ---- attention (round-3 proven inner loops)
    {
        const int n = tid >> 3, sub = tid & 7;
        const int m0 = sub * 8;
        #pragma unroll 1
        for (int h = 0; h < NH; h++) {
            const int hb = h * HD;
            u64t qd[HD];
            #pragma unroll
            for (int dd = 0; dd < HD; dd++) qd[dd] = dup2(qbuf[n * 100 + hb + dd]);

            u64t p2[4] = {0ull, 0ull, 0ull, 0ull};
            #pragma unroll
            for (int dd = 0; dd < HD; dd++) {
                const float* kp = kT + (hb + dd) * 68 + m0;
                u64t k01, k23, k45, k67;
                ldsv2b64(k01, k23, kp);
                ldsv2b64(k45, k67, kp + 4);
                fma2(p2[0], qd[dd], k01); fma2(p2[1], qd[dd], k23);
                fma2(p2[2], qd[dd], k45); fma2(p2[3], qd[dd], k67);
            }
            float p[8];
            #pragma unroll
            for (int i = 0; i < 4; i++) { float2 t = up2(p2[i]); p[2*i] = t.x; p[2*i+1] = t.y; }
            #pragma unroll
            for (int i = 0; i < 8; i++) {
                int rdx = rel[n * 64 + m0 + i];
                p[i] = p[i] * 0.25f + sbias[rdx * NH + h];
            }
            float mx = -1e30f;
            #pragma unroll
            for (int i = 0; i < 8; i++) mx = fmaxf(mx, p[i]);
            mx = fmaxf(mx, __shfl_xor_sync(0xffffffffu, mx, 1));
            mx = fmaxf(mx, __shfl_xor_sync(0xffffffffu, mx, 2));
            mx = fmaxf(mx, __shfl_xor_sync(0xffffffffu, mx, 4));
            float sum = 0.f;
            #pragma unroll
            for (int i = 0; i < 8; i++) { p[i] = __expf(p[i] - mx); sum += p[i]; }
            sum += __shfl_xor_sync(0xffffffffu, sum, 1);
            sum += __shfl_xor_sync(0xffffffffu, sum, 2);
            sum += __shfl_xor_sync(0xffffffffu, sum, 4);
            float inv = 1.f / sum;
            #pragma unroll
            for (int i = 0; i < 8; i++) sbuf[n * 68 + m0 + i] = p[i] * inv;
            __syncwarp();

            float o0 = 0.f, o1 = 0.f, o0b = 0.f, o1b = 0.f;
            const float* vb = vbuf + hb + sub * 2;
            #pragma unroll
            for (int m4 = 0; m4 < 16; m4++) {
                float4 pr = ldsf4(sbuf + n * 68 + m4 * 4);
                const float* vm = vb + (m4 * 4) * 100;
                float2 v0 = ldsf2(vm);         o0  += pr.x * v0.x; o1  += pr.x * v0.y;
                float2 v1 = ldsf2(vm + 100);   o0b += pr.y * v1.x; o1b += pr.y * v1.y;
                float2 v2 = ldsf2(vm + 200);   o0  += pr.z * v2.x; o1  += pr.z * v2.y;
                float2 v3 = ldsf2(vm + 300);   o0b += pr.w * v3.x; o1b += pr.w * v3.y;
            }
            oT[(hb + sub * 2) * 68 + n]     = o0 + o0b;
            oT[(hb + sub * 2 + 1) * 68 + n] = o1 + o1b;
            __syncwarp();
        }
    }
    __syncthreads();

    // ---- proj [64x96]@[96x96], split-K 2, row-pair packing + residual
    {
        const int kh = tid >> 8;
        const int t2 = tid & 255;
        const int rg = t2 >> 5, lane = t2 & 31;
        const int r0 = rg * 8;
        u64t acc[4][3];
        #pragma unroll
        for (int j = 0; j < 3; j++) {
            u64t bj = (kh == 0) ? dup2(__ldg(proj_b + lane + 32 * j)) : 0ull;
            #pragma unroll
            for (int p = 0; p < 4; p++) acc[p][j] = bj;
        }
        const int k0 = kh * 48;
        #pragma unroll 2
        for (int kk = 0; kk < 48; kk++) {
            int k = k0 + kk;
            u64t a[4];
            ldsv2b64(a[0], a[1], oT + k * 68 + r0);
            ldsv2b64(a[2], a[3], oT + k * 68 + r0 + 4);
            const float* wr = proj_w + k * 96 + lane;
            #pragma unroll
            for (int j = 0; j < 3; j++) {
                u64t wd = dup2(__ldg(wr + 32 * j));
                #pragma unroll
                for (int p = 0; p < 4; p++) fma2(acc[p][j], a[p], wd);
            }
        }
        float* red = qbuf;   // [64][98]
        if (kh == 1) {
            #pragma unroll
            for (int p = 0; p < 4; p++) {
                int r = r0 + 2 * p;
                #pragma unroll
                for (int j = 0; j < 3; j++) {
                    int c = lane + 32 * j;
                    float2 t = up2(acc[p][j]);
                    red[r * 98 + c] = t.x;
                    red[(r + 1) * 98 + c] = t.y;
                }
            }
        }
        __syncthreads();
        if (kh == 0) {
            #pragma unroll
            for (int p = 0; p < 4; p++) {
                int r = r0 + 2 * p;
                size_t b0 = (size_t)(bb * LTOK + srcidx[r]) * C;
                size_t b1 = (size_t)(bb * LTOK + srcidx[r + 1]) * C;
                #pragma unroll
                for (int j = 0; j < 3; j++) {
                    int c = lane + 32 * j;
                    float2 t = up2(acc[p][j]);
                    g_ybuf[b0 + c] = x[b0 + c] + t.x + red[r * 98 + c];
                    g_ybuf[b1 + c] = x[b1 + c] + t.y + red[(r + 1) * 98 + c];
                }
            }
        }
    }
}

// ===========================================================================
// Kernel B: LN2 + MLP
// ===========================================================================
#define B_HID 0        // hidT [384][68]
#define B_H2D 26112    // h2dup [96][130]; reused as red [3][64][98]
#define B_TOT 44928

__global__ __launch_bounds__(512, 1)
void mlp_kernel(const float* __restrict__ g2, const float* __restrict__ b2,
                const float* __restrict__ w1, const float* __restrict__ bb1,
                const float* __restrict__ w2, const float* __restrict__ bb2,
                float* __restrict__ out)
{
    extern __shared__ float smf[];
    float* hidT  = smf + B_HID;
    float* h2dup = smf + B_H2D;

    const int tid = threadIdx.x;
    const int t0 = blockIdx.x * NW;

    // ---- LN2 -> h2dup[c][2n] dup pairs
    {
        const int n = tid >> 3, q8 = tid & 7;
        const float* yr = g_ybuf + (size_t)(t0 + n) * C + q8 * 12;
        float v[12]; float s = 0.f, ss = 0.f;
        #pragma unroll
        for (int j = 0; j < 12; j++) { float t = yr[j]; v[j] = t; s += t; ss += t * t; }
        s  += __shfl_xor_sync(0xffffffffu, s, 1);  ss += __shfl_xor_sync(0xffffffffu, ss, 1);
        s  += __shfl_xor_sync(0xffffffffu, s, 2);  ss += __shfl_xor_sync(0xffffffffu, ss, 2);
        s  += __shfl_xor_sync(0xffffffffu, s, 4);  ss += __shfl_xor_sync(0xffffffffu, ss, 4);
        float mean = s * (1.f / 96.f);
        float var  = ss * (1.f / 96.f) - mean * mean;
        float rstd = rsqrtf(var + 1e-5f);
        #pragma unroll
        for (int j = 0; j < 12; j++) {
            int c = q8 * 12 + j;
            float val = (v[j] - mean) * rstd * __ldg(g2 + c) + __ldg(b2 + c);
            stsb64(h2dup + c * 130 + 2 * n, dup2(val));
        }
    }
    __syncthreads();

    // ---- GEMM1 [64x96]@[96x384] + GELU -> hidT[c][n]
    // rg = tid>>5 (16 x 4 rows), lane = tid&31, col pairs 2*lane+64j, j<6
    {
        const int rg = tid >> 5, lane = tid & 31;
        const int r0 = rg * 4;
        u64t acc[4][6];
        #pragma unroll
        for (int j = 0; j < 6; j++) {
            float2 bv = __ldg((const float2*)(bb1 + 2 * lane + 64 * j));
            u64t bj = pk2(bv.x, bv.y);
            #pragma unroll
            for (int r = 0; r < 4; r++) acc[r][j] = bj;
        }
        #pragma unroll 2
        for (int k = 0; k < C; k++) {
            u64t ad[4];
            #pragma unroll
            for (int r = 0; r < 4; r++) ad[r] = ldsb64(h2dup + k * 130 + 2 * (r0 + r));
            const float* wr = w1 + k * MLPH;
            #pragma unroll
            for (int j = 0; j < 6; j++) {
                u64t wp = ldg64(wr + 2 * lane + 64 * j);
                #pragma unroll
                for (int r = 0; r < 4; r++) fma2(acc[r][j], ad[r], wp);
            }
        }
        #pragma unroll
        for (int r = 0; r < 4; r++) {
            int row = r0 + r;
            #pragma unroll
            for (int j = 0; j < 6; j++) {
                int c = 2 * lane + 64 * j;
                float2 t = up2(acc[r][j]);
                float gx = 0.5f * t.x * (1.0f + erff(t.x * 0.70710678118654752f));
                float gy = 0.5f * t.y * (1.0f + erff(t.y * 0.70710678118654752f));
                hidT[c * 68 + row] = gx;
                hidT[(c + 1) * 68 + row] = gy;
            }
        }
    }
    __syncthreads();

    // ---- GEMM2 [64x384]@[384x96], split-K 4, row-pair packing + residual
    // kh = tid>>7 (4), rg = (tid>>5)&3 (4 x 16 rows), lane = tid&31
    {
        const int kh = tid >> 7;
        const int rg = (tid >> 5) & 3, lane = tid & 31;
        const int r0 = rg * 16;
        u64t acc[8][3];
        #pragma unroll
        for (int j = 0; j < 3; j++) {
            u64t bj = (kh == 0) ? dup2(__ldg(bb2 + lane + 32 * j)) : 0ull;
            #pragma unroll
            for (int p = 0; p < 8; p++) acc[p][j] = bj;
        }
        const int k0 = kh * 96;
        #pragma unroll 2
        for (int kk = 0; kk < 96; kk++) {
            int k = k0 + kk;
            u64t a[8];
            const float* hp = hidT + k * 68 + r0;
            ldsv2b64(a[0], a[1], hp);
            ldsv2b64(a[2], a[3], hp + 4);
            ldsv2b64(a[4], a[5], hp + 8);
            ldsv2b64(a[6], a[7], hp + 12);
            const float* wr = w2 + k * 96 + lane;
            #pragma unroll
            for (int j = 0; j < 3; j++) {
                u64t wd = dup2(__ldg(wr + 32 * j));
                #pragma unroll
                for (int p = 0; p < 8; p++) fma2(acc[p][j], a[p], wd);
            }
        }
        float* red = h2dup;   // [3][64][98]
        if (kh > 0) {
            float* rp = red + (kh - 1) * 6272;
            #pragma unroll
            for (int p = 0; p < 8; p++) {
                int r = r0 + 2 * p;
                #pragma unroll
                for (int j = 0; j < 3; j++) {
                    int c = lane + 32 * j;
                    float2 t = up2(acc[p][j]);
                    rp[r * 98 + c] = t.x;
                    rp[(r + 1) * 98 + c] = t.y;
                }
            }
        }
        __syncthreads();
        if (kh == 0) {
            #pragma unroll
            for (int p = 0; p < 8; p++) {
                int r = r0 + 2 * p;
                size_t b0 = (size_t)(t0 + r) * C;
                size_t b1 = (size_t)(t0 + r + 1) * C;
                #pragma unroll
                for (int j = 0; j < 3; j++) {
                    int c = lane + 32 * j;
                    float2 t = up2(acc[p][j]);
                    float s0 = t.x + red[r * 98 + c] + red[6272 + r * 98 + c]
                                   + red[12544 + r * 98 + c];
                    float s1 = t.y + red[(r + 1) * 98 + c] + red[6272 + (r + 1) * 98 + c]
                                   + red[12544 + (r + 1) * 98 + c];
                    out[b0 + c] = g_ybuf[b0 + c] + s0;
                    out[b1 + c] = g_ybuf[b1 + c] + s1;
                }
            }
        }
    }
}

// ---------------------------------------------------------------------------
extern "C" void kernel_launch(void* const* d_in, const int* in_sizes, int n_in,
                              void* d_out, int out_size)
{
    const float* x        = (const float*)d_in[0];
    const float* norm1_g  = (const float*)d_in[1];
    const float* norm1_b  = (const float*)d_in[2];
    const float* qkv_w    = (const float*)d_in[3];
    const float* qkv_b    = (const float*)d_in[4];
    const float* proj_w   = (const float*)d_in[5];
    const float* proj_b   = (const float*)d_in[6];
    const float* bias_tab = (const float*)d_in[7];
    const float* norm2_g  = (const float*)d_in[8];
    const float* norm2_b  = (const float*)d_in[9];
    const float* mlp_w1   = (const float*)d_in[10];
    const float* mlp_b1   = (const float*)d_in[11];
    const float* mlp_w2   = (const float*)d_in[12];
    const float* mlp_b2   = (const float*)d_in[13];
    float* out = (float*)d_out;

    cudaFuncSetAttribute(win_attn_kernel,
                         cudaFuncAttributeMaxDynamicSharedMemorySize, A_TOT * 4);
    cudaFuncSetAttribute(mlp_kernel,
                         cudaFuncAttributeMaxDynamicSharedMemorySize, B_TOT * 4);

    win_attn_kernel<<<NTILE, 512, A_TOT * 4>>>(x, norm1_g, norm1_b,
                                               qkv_w, qkv_b, proj_w, proj_b,
                                               bias_tab);
    mlp_kernel<<<NTILE, 512, B_TOT * 4>>>(norm2_g, norm2_b,
                                          mlp_w1, mlp_b1, mlp_w2, mlp_b2, out);
}